// round 13
// baseline (speedup 1.0000x reference)
#include <cuda_runtime.h>
#include <cuda_fp16.h>

// Edge_27547920236817: B=16, C=3, H=W=512 f32 in; out (B, C*8, H, W) f32.
// R7 (= R4 with compile fix): 2 x-adjacent pixels per thread; the 22 unique
// e-sum tanh terms computed as tanh.approx.f16x2 (args packed across the
// pixel pair), unpacked and summed in f32. Gates, sign sigmoids and
// ad-multiplier tanhs remain f32 MUFU.TANH.
// MUFU per pixel: 33 -> 22 (11 f16x2-halves + 11 f32).
// Memory instrs per pixel: 19 LDG + 8 STG -> 11 LDG + 4 STG.64.

#define HH 512
#define WW 512

__device__ __forceinline__ float th(float x) {
    float y;
    asm("tanh.approx.f32 %0, %1;" : "=f"(y) : "f"(x));
    return y;
}

// tanh.approx.f16x2 on (a0, a1); accumulate w*tanh into f32 sums T[0], T[1]
__device__ __forceinline__ void acc2(float* T, float a0, float a1, float w = 1.0f) {
    __half2 h = __floats2half2_rn(a0, a1);
    unsigned uin, uout;
    uin = *reinterpret_cast<unsigned*>(&h);
    asm("tanh.approx.f16x2 %0, %1;" : "=r"(uout) : "r"(uin));
    __half2 t = *reinterpret_cast<__half2*>(&uout);
    float2 tf = __half22float2(t);
    T[0] = fmaf(w, tf.x, T[0]);
    T[1] = fmaf(w, tf.y, T[1]);
}

__device__ __forceinline__ float2 ldg2(const float* p) {
    return *reinterpret_cast<const float2*>(p);
}

__global__ void __launch_bounds__(256) edge_kernel(const float* __restrict__ in,
                                                   float* __restrict__ out) {
    int idx = blockIdx.x * blockDim.x + threadIdx.x;   // one thread = 2 pixels
    int x  = (idx & 255) << 1;         // even
    int y  = (idx >> 8) & (HH - 1);
    int bc = idx >> 17;                // b*3 + c
    int c  = bc - (bc / 3) * 3;
    int b  = bc / 3;

    float* o = out + (((b * 24 + c * 8) << 18) + (y << 9) + x);

    if (x < 2 || x >= WW - 2 || y < 2 || y >= HH - 2) {
        float2 z = make_float2(0.0f, 0.0f);
        #pragma unroll
        for (int k = 0; k < 8; k++) *reinterpret_cast<float2*>(o + (k << 18)) = z;
        return;
    }

    int cm = (c + 2) % 3;
    int cp = (c + 1) % 3;

    const float* p  = in + (bc << 18);
    const float* pa = in + ((b * 3 + cm) << 18);
    const float* pc = in + ((b * 3 + cp) << 18);

    int r   = (y << 9) + x;
    int rm1 = r - WW, rp1 = r + WW, rm2 = r - 2 * WW;

    const float S = 5.0f;

    // ---- loads (pre-scaled by 5) ----
    // own channel
    float2 Vm2 = ldg2(p + rm2);         Vm2.x *= S; Vm2.y *= S;
    float  um1L = S * __ldg(p + rm1 - 1);
    float2 Um1  = ldg2(p + rm1);        Um1.x *= S; Um1.y *= S;
    float  um1R = S * __ldg(p + rm1 + 2);
    float  u0L  = S * __ldg(p + r - 1);
    float2 U0   = ldg2(p + r);          U0.x  *= S; U0.y  *= S;
    float  u0R  = S * __ldg(p + r + 2);
    float  up1L = S * __ldg(p + rp1 - 1);
    float2 Up1  = ldg2(p + rp1);        Up1.x *= S; Up1.y *= S;
    float  up1R = S * __ldg(p + rp1 + 2);
    // channel cm
    float  aL  = S * __ldg(pa + r - 1);
    float2 A0  = ldg2(pa + r);          A0.x *= S; A0.y *= S;
    float  aR  = S * __ldg(pa + r + 2);
    float2 Am1 = ldg2(pa + rm1);        Am1.x *= S; Am1.y *= S;
    float  a2L = S * __ldg(pa + rm2 - 1);
    float2 A2  = ldg2(pa + rm2);        A2.x *= S; A2.y *= S;
    float  a2R = S * __ldg(pa + rm2 + 2);
    // channel cp
    float2 Cm1 = ldg2(pc + rm1);        Cm1.x *= S; Cm1.y *= S;
    float  c2L = S * __ldg(pc + rm2 - 1);
    float  c2C = S * __ldg(pc + rm2);
    float  c0L = S * __ldg(pc + r - 1);
    float  c0C = S * __ldg(pc + r);

    // ---- per-lane neighborhoods ----
    float v00[2]   = { U0.x,  U0.y  };
    float v0m1[2]  = { u0L,   U0.x  };
    float v0p1[2]  = { U0.y,  u0R   };
    float vm1m1[2] = { um1L,  Um1.x };
    float vm10[2]  = { Um1.x, Um1.y };
    float vm1p1[2] = { Um1.y, um1R  };
    float vp1m1[2] = { up1L,  Up1.x };
    float vp10[2]  = { Up1.x, Up1.y };
    float vp1p1[2] = { Up1.y, up1R  };
    float vm20[2]  = { Vm2.x, Vm2.y };
    float a00[2]   = { A0.x,  A0.y  };
    float a0m1[2]  = { aL,    A0.x  };
    float a0p1[2]  = { A0.y,  aR    };
    float am10[2]  = { Am1.x, Am1.y };
    float am2m1[2] = { a2L,   A2.x  };
    float am2p1[2] = { A2.y,  a2R   };
    float cm10[2]  = { Cm1.x, Cm1.y };
    float cm2m1[2] = { c2L,   c2C   };
    float c0m1[2]  = { c0L,   c0C   };

    // ---- diffs (scaled) ----
    float d10[2], dn10[2], d01[2], dn01[2], d11[2], dnn11[2], dn11[2], d1n1[2];
    float rd01a[2], rdn01a[2], rd10u[2], rdn10u[2], rd01u[2];
    float rdn11b[2], rd1n1b[2], rd11b[2], rd11c[2], rdn11c[2];
    #pragma unroll
    for (int i = 0; i < 2; i++) {
        d10[i]   = vm10[i]  - v00[i];
        dn10[i]  = vp10[i]  - v00[i];
        d01[i]   = v0m1[i]  - v00[i];
        dn01[i]  = v0p1[i]  - v00[i];
        d11[i]   = vm1m1[i] - v00[i];
        dnn11[i] = vp1p1[i] - v00[i];
        dn11[i]  = vp1m1[i] - v00[i];
        d1n1[i]  = vm1p1[i] - v00[i];
        rd01a[i]  = a0m1[i] - a00[i];      // rl(.,(1,0))
        rdn01a[i] = a0p1[i] - a00[i];
        rd10u[i]  = vm20[i]  - vm10[i];    // rl(.,(0,1))
        rdn10u[i] = v00[i]   - vm10[i];
        rd01u[i]  = vm1m1[i] - vm10[i];
        rdn11b[i] = a0m1[i]  - am10[i];    // rl(.,(1,1))
        rd1n1b[i] = am2p1[i] - am10[i];
        rd11b[i]  = am2m1[i] - am10[i];
        rd11c[i]  = cm2m1[i] - cm10[i];    // rl(.,(-1,1))
        rdn11c[i] = c0m1[i]  - cm10[i];
    }

    // ---- per-lane ad bases (f32 tanh) ----
    float ad10[2], thad10[2], ad01[2], ad11[2], adn11[2];
    #pragma unroll
    for (int i = 0; i < 2; i++) {
        float ad10r = fabsf(d10[i]);
        ad10[i]  = ad10r * fmaf(0.5f, th(ad10r), 0.5f);
        thad10[i] = th(ad10[i]);
        ad01[i]  = fabsf(d01[i]) * fmaf(0.5f, thad10[i], 0.5f);
        float ad11r = fabsf(d11[i]);
        ad11[i]  = ad11r * fmaf(0.5f, th(ad11r), 0.5f);
        adn11[i] = fabsf(dn11[i]);
    }

    // ---- e-sums: f16x2 tanh terms, f32 accumulation ----
    float T10[2] = {0.f, 0.f}, T01[2] = {0.f, 0.f}, T11[2] = {0.f, 0.f}, Tn11[2] = {0.f, 0.f};

    acc2(T10, ad10[0] - fabsf(d01[0]),   ad10[1] - fabsf(d01[1]));
    acc2(T10, ad10[0] - fabsf(dn01[0]),  ad10[1] - fabsf(dn01[1]));
    acc2(T10, ad10[0] - fabsf(dn10[0]),  ad10[1] - fabsf(dn10[1]));
    acc2(T10, ad10[0] - fabsf(rd01a[0]), ad10[1] - fabsf(rd01a[1]), 2.0f);
    acc2(T10, ad10[0] - fabsf(rdn01a[0]),ad10[1] - fabsf(rdn01a[1]));

    acc2(T01, ad01[0] - fabsf(d10[0]),   ad01[1] - fabsf(d10[1]));
    acc2(T01, ad01[0] - fabsf(dn10[0]),  ad01[1] - fabsf(dn10[1]));
    acc2(T01, ad01[0] - fabsf(dn01[0]),  ad01[1] - fabsf(dn01[1]));
    acc2(T01, ad01[0] - fabsf(rd10u[0]), ad01[1] - fabsf(rd10u[1]));
    acc2(T01, ad01[0] - fabsf(rdn10u[0]),ad01[1] - fabsf(rdn10u[1]));
    acc2(T01, ad01[0] - fabsf(rd01u[0]), ad01[1] - fabsf(rd01u[1]));

    acc2(T11, ad11[0] - fabsf(dn11[0]),  ad11[1] - fabsf(dn11[1]));
    acc2(T11, ad11[0] - fabsf(d1n1[0]),  ad11[1] - fabsf(d1n1[1]));
    acc2(T11, ad11[0] - fabsf(dnn11[0]), ad11[1] - fabsf(dnn11[1]));
    acc2(T11, ad11[0] - fabsf(rdn11b[0]),ad11[1] - fabsf(rdn11b[1]));
    acc2(T11, ad11[0] - fabsf(rd1n1b[0]),ad11[1] - fabsf(rd1n1b[1]));
    acc2(T11, ad11[0] - fabsf(rd11b[0]), ad11[1] - fabsf(rd11b[1]));

    acc2(Tn11, adn11[0] - fabsf(d11[0]),   adn11[1] - fabsf(d11[1]));
    acc2(Tn11, adn11[0] - fabsf(d1n1[0]),  adn11[1] - fabsf(d1n1[1]));
    acc2(Tn11, adn11[0] - fabsf(dnn11[0]), adn11[1] - fabsf(dnn11[1]));
    acc2(Tn11, adn11[0] - fabsf(rd11c[0]), adn11[1] - fabsf(rd11c[1]));
    acc2(Tn11, adn11[0] - fabsf(rdn11c[0]),adn11[1] - fabsf(rdn11c[1]), 2.0f);

    // ---- gates + outputs (f32) ----
    float2 O[8];
    #pragma unroll
    for (int i = 0; i < 2; i++) {
        float g10 = fmaf(0.5f, th(fmaf(2.5f, T10[i], -5.0f)), 0.5f);
        float s10 = fmaf(0.5f, th(d10[i]), 0.5f);
        float g01 = fmaf(0.5f, th(fmaf(2.5f, T01[i], -5.0f)), 0.5f);
        float s01 = fmaf(0.5f, th(d01[i]), 0.5f);
        float g11 = fmaf(0.5f, th(fmaf(2.5f, T11[i], -5.0f)), 0.5f);
        float s11 = fmaf(0.5f, th(d11[i]), 0.5f);
        float gn11 = fmaf(0.5f, th(fmaf(2.5f, Tn11[i], -5.0f)), 0.5f);
        float sn11 = fmaf(0.5f, th(dn11[i]), 0.5f);
        float e0 = g10 * s10;
        float e2 = g01 * s01;
        float e4 = g11 * s11;
        float e6 = gn11 * sn11;
        float* oi = i ? &O[0].y : &O[0].x;
        oi[0*2] = e0;        oi[1*2] = g10 - e0;
        oi[2*2] = e2;        oi[3*2] = e2;        // reference quirk: e01n == e01
        oi[4*2] = e4;        oi[5*2] = g11 - e4;
        oi[6*2] = e6;        oi[7*2] = gn11 - e6;
    }

    #pragma unroll
    for (int k = 0; k < 8; k++)
        *reinterpret_cast<float2*>(o + (k << 18)) = O[k];
}

extern "C" void kernel_launch(void* const* d_in, const int* in_sizes, int n_in,
                              void* d_out, int out_size) {
    const float* x = (const float*)d_in[0];
    float* out = (float*)d_out;
    int total_threads = 16 * 3 * HH * (WW / 2);
    edge_kernel<<<total_threads / 256, 256>>>(x, out);
}

// round 14
// speedup vs baseline: 1.5922x; 1.5922x over previous
#include <cuda_runtime.h>
#include <cuda_fp16.h>

// Edge_27547920236817: B=16, C=3, H=W=512 f32 in; out (B, C*8, H, W) f32.
// R13: 2 px/thread. 22 e-sum tanh terms as tanh.approx.f16x2 (args packed
// across the pixel pair via F2FP = ALU pipe). e-sums accumulated in f16x2
// (HADD2/HFMA2, fma pipe), SHIFTED by -2 so partials near the gate
// transition are small-magnitude (small f16 ulp). Only the 4 final group
// sums are unpacked, via an ALU bit-trick (no F2F on the XU pipe).
// Gates / signs / ad-chain are f32 MUFU.TANH.
// XU ops per pixel: 33 (R3) -> 22.  No local-memory arrays.

#define HH 512
#define WW 512

__device__ __forceinline__ float th(float x) {
    float y;
    asm("tanh.approx.f32 %0, %1;" : "=f"(y) : "f"(x));
    return y;
}

// pack (a0,a1) -> f16x2 (F2FP, ALU pipe), tanh.approx.f16x2 (XU)
__device__ __forceinline__ __half2 th2(float a0, float a1) {
    __half2 h = __floats2half2_rn(a0, a1);
    unsigned u = *reinterpret_cast<unsigned*>(&h);
    unsigned v;
    asm("tanh.approx.f16x2 %0, %1;" : "=r"(v) : "r"(u));
    return *reinterpret_cast<__half2*>(&v);
}

// f16x2 -> two f32 via integer ops only (no F2F). Exact for normal halves;
// |err| <= 2^-14 for zero/subnormal inputs (harmless: feeds a tanh arg).
__device__ __forceinline__ float2 h2f2(__half2 h) {
    unsigned u = *reinterpret_cast<unsigned*>(&h);
    unsigned lo = ((u & 0x8000u) << 16) | (((u & 0x7fffu) << 13) + 0x38000000u);
    unsigned hi = (u & 0x80000000u)     | (((u >> 3) & 0x0FFFE000u) + 0x38000000u);
    return make_float2(__uint_as_float(lo), __uint_as_float(hi));
}

__device__ __forceinline__ float2 ldg2(const float* p) {
    return *reinterpret_cast<const float2*>(p);
}

__global__ void __launch_bounds__(256) edge_kernel(const float* __restrict__ in,
                                                   float* __restrict__ out) {
    int idx = blockIdx.x * blockDim.x + threadIdx.x;   // one thread = 2 pixels
    int x  = (idx & 255) << 1;
    int y  = (idx >> 8) & (HH - 1);
    int bc = idx >> 17;                // b*3 + c
    int c  = bc - (bc / 3) * 3;
    int b  = bc / 3;

    float* o = out + (((b * 24 + c * 8) << 18) + (y << 9) + x);

    if (x < 2 || x >= WW - 2 || y < 2 || y >= HH - 2) {
        float2 z = make_float2(0.0f, 0.0f);
        #pragma unroll
        for (int k = 0; k < 8; k++) *reinterpret_cast<float2*>(o + (k << 18)) = z;
        return;
    }

    int cm = (c + 2) % 3;
    int cp = (c + 1) % 3;

    const float* p  = in + (bc << 18);
    const float* pa = in + ((b * 3 + cm) << 18);
    const float* pc = in + ((b * 3 + cp) << 18);

    int r   = (y << 9) + x;
    int rm1 = r - WW, rp1 = r + WW, rm2 = r - 2 * WW;

    const float S = 5.0f;

    // ---- loads (pre-scaled by 5) ----
    float2 Vm2 = ldg2(p + rm2);         Vm2.x *= S; Vm2.y *= S;
    float  um1L = S * __ldg(p + rm1 - 1);
    float2 Um1  = ldg2(p + rm1);        Um1.x *= S; Um1.y *= S;
    float  um1R = S * __ldg(p + rm1 + 2);
    float  u0L  = S * __ldg(p + r - 1);
    float2 U0   = ldg2(p + r);          U0.x  *= S; U0.y  *= S;
    float  u0R  = S * __ldg(p + r + 2);
    float  up1L = S * __ldg(p + rp1 - 1);
    float2 Up1  = ldg2(p + rp1);        Up1.x *= S; Up1.y *= S;
    float  up1R = S * __ldg(p + rp1 + 2);
    float  aL  = S * __ldg(pa + r - 1);
    float2 A0  = ldg2(pa + r);          A0.x *= S; A0.y *= S;
    float  aR  = S * __ldg(pa + r + 2);
    float2 Am1 = ldg2(pa + rm1);        Am1.x *= S; Am1.y *= S;
    float  a2L = S * __ldg(pa + rm2 - 1);
    float2 A2  = ldg2(pa + rm2);        A2.x *= S; A2.y *= S;
    float  a2R = S * __ldg(pa + rm2 + 2);
    float2 Cm1 = ldg2(pc + rm1);        Cm1.x *= S; Cm1.y *= S;
    float  c2L = S * __ldg(pc + rm2 - 1);
    float  c2C = S * __ldg(pc + rm2);
    float  c0L = S * __ldg(pc + r - 1);
    float  c0C = S * __ldg(pc + r);

    // ---- per-lane neighborhoods (constant-index arrays, fully unrolled) ----
    float v00[2]   = { U0.x,  U0.y  };
    float v0m1[2]  = { u0L,   U0.x  };
    float v0p1[2]  = { U0.y,  u0R   };
    float vm1m1[2] = { um1L,  Um1.x };
    float vm10[2]  = { Um1.x, Um1.y };
    float vm1p1[2] = { Um1.y, um1R  };
    float vp1m1[2] = { up1L,  Up1.x };
    float vp10[2]  = { Up1.x, Up1.y };
    float vp1p1[2] = { Up1.y, up1R  };
    float vm20[2]  = { Vm2.x, Vm2.y };
    float a00[2]   = { A0.x,  A0.y  };
    float a0m1[2]  = { aL,    A0.x  };
    float a0p1[2]  = { A0.y,  aR    };
    float am10[2]  = { Am1.x, Am1.y };
    float am2m1[2] = { a2L,   A2.x  };
    float am2p1[2] = { A2.y,  a2R   };
    float cm10[2]  = { Cm1.x, Cm1.y };
    float cm2m1[2] = { c2L,   c2C   };
    float c0m1[2]  = { c0L,   c0C   };

    // ---- diffs (scaled) ----
    float d10[2], dn10[2], d01[2], dn01[2], d11[2], dnn11[2], dn11[2], d1n1[2];
    float rd01a[2], rdn01a[2], rd10u[2], rdn10u[2], rd01u[2];
    float rdn11b[2], rd1n1b[2], rd11b[2], rd11c[2], rdn11c[2];
    #pragma unroll
    for (int i = 0; i < 2; i++) {
        d10[i]   = vm10[i]  - v00[i];
        dn10[i]  = vp10[i]  - v00[i];
        d01[i]   = v0m1[i]  - v00[i];
        dn01[i]  = v0p1[i]  - v00[i];
        d11[i]   = vm1m1[i] - v00[i];
        dnn11[i] = vp1p1[i] - v00[i];
        dn11[i]  = vp1m1[i] - v00[i];
        d1n1[i]  = vm1p1[i] - v00[i];
        rd01a[i]  = a0m1[i] - a00[i];
        rdn01a[i] = a0p1[i] - a00[i];
        rd10u[i]  = vm20[i]  - vm10[i];
        rdn10u[i] = v00[i]   - vm10[i];
        rd01u[i]  = vm1m1[i] - vm10[i];
        rdn11b[i] = a0m1[i]  - am10[i];
        rd1n1b[i] = am2p1[i] - am10[i];
        rd11b[i]  = am2m1[i] - am10[i];
        rd11c[i]  = cm2m1[i] - cm10[i];
        rdn11c[i] = c0m1[i]  - cm10[i];
    }

    // ---- ad bases (f32 tanh: 3 XU per pixel) ----
    float ad10[2], thad10[2], ad01[2], ad11[2], adn11[2];
    #pragma unroll
    for (int i = 0; i < 2; i++) {
        float ad10r = fabsf(d10[i]);
        ad10[i]  = ad10r * fmaf(0.5f, th(ad10r), 0.5f);
        thad10[i] = th(ad10[i]);
        ad01[i]  = fabsf(d01[i]) * fmaf(0.5f, thad10[i], 0.5f);
        float ad11r = fabsf(d11[i]);
        ad11[i]  = ad11r * fmaf(0.5f, th(ad11r), 0.5f);
        adn11[i] = fabsf(dn11[i]);
    }

    const __half2 M2 = __floats2half2_rn(-2.0f, -2.0f);
    const __half2 TW = __floats2half2_rn( 2.0f,  2.0f);

    // ---- group 10: weights (1,1,1,2,1); accumulate T-2 in f16x2 ----
    {
        __half2 ta = th2(ad10[0] - fabsf(d01[0]),   ad10[1] - fabsf(d01[1]));
        __half2 tb = th2(ad10[0] - fabsf(dn01[0]),  ad10[1] - fabsf(dn01[1]));
        __half2 tc = th2(ad10[0] - fabsf(dn10[0]),  ad10[1] - fabsf(dn10[1]));
        __half2 td = th2(ad10[0] - fabsf(rd01a[0]), ad10[1] - fabsf(rd01a[1]));   // w=2
        __half2 te = th2(ad10[0] - fabsf(rdn01a[0]),ad10[1] - fabsf(rdn01a[1]));
        __half2 q = __hfma2(td, TW, M2);
        q = __hadd2(q, __hadd2(ta, tb));
        q = __hadd2(q, __hadd2(tc, te));
        float2 Tm2 = h2f2(q);   // T - 2 per pixel

        __half2 sa = th2(ad01[0] - fabsf(d10[0]),   ad01[1] - fabsf(d10[1]));
        __half2 sb = th2(ad01[0] - fabsf(dn10[0]),  ad01[1] - fabsf(dn10[1]));
        __half2 sc = th2(ad01[0] - fabsf(dn01[0]),  ad01[1] - fabsf(dn01[1]));
        __half2 sd = th2(ad01[0] - fabsf(rd10u[0]), ad01[1] - fabsf(rd10u[1]));
        __half2 se = th2(ad01[0] - fabsf(rdn10u[0]),ad01[1] - fabsf(rdn10u[1]));
        __half2 sf = th2(ad01[0] - fabsf(rd01u[0]), ad01[1] - fabsf(rd01u[1]));
        __half2 q2 = __hadd2(__hadd2(sa, sb), M2);
        q2 = __hadd2(q2, __hadd2(sc, sd));
        q2 = __hadd2(q2, __hadd2(se, sf));
        float2 T2m2 = h2f2(q2);

        __half2 ua = th2(ad11[0] - fabsf(dn11[0]),  ad11[1] - fabsf(dn11[1]));
        __half2 ub = th2(ad11[0] - fabsf(d1n1[0]),  ad11[1] - fabsf(d1n1[1]));
        __half2 uc = th2(ad11[0] - fabsf(dnn11[0]), ad11[1] - fabsf(dnn11[1]));
        __half2 ud = th2(ad11[0] - fabsf(rdn11b[0]),ad11[1] - fabsf(rdn11b[1]));
        __half2 ue = th2(ad11[0] - fabsf(rd1n1b[0]),ad11[1] - fabsf(rd1n1b[1]));
        __half2 uf = th2(ad11[0] - fabsf(rd11b[0]), ad11[1] - fabsf(rd11b[1]));
        __half2 q3 = __hadd2(__hadd2(ua, ub), M2);
        q3 = __hadd2(q3, __hadd2(uc, ud));
        q3 = __hadd2(q3, __hadd2(ue, uf));
        float2 T3m2 = h2f2(q3);

        __half2 wa = th2(adn11[0] - fabsf(d11[0]),   adn11[1] - fabsf(d11[1]));
        __half2 wb = th2(adn11[0] - fabsf(d1n1[0]),  adn11[1] - fabsf(d1n1[1]));
        __half2 wc = th2(adn11[0] - fabsf(dnn11[0]), adn11[1] - fabsf(dnn11[1]));
        __half2 wd = th2(adn11[0] - fabsf(rd11c[0]), adn11[1] - fabsf(rd11c[1]));
        __half2 we = th2(adn11[0] - fabsf(rdn11c[0]),adn11[1] - fabsf(rdn11c[1])); // w=2
        __half2 q4 = __hfma2(we, TW, M2);
        q4 = __hadd2(q4, __hadd2(wa, wb));
        q4 = __hadd2(q4, __hadd2(wc, wd));
        float2 T4m2 = h2f2(q4);

        // ---- gates + signs + outputs (f32; 8 XU per pixel) ----
        float g10_0 = fmaf(0.5f, th(2.5f * Tm2.x),  0.5f);
        float g10_1 = fmaf(0.5f, th(2.5f * Tm2.y),  0.5f);
        float g01_0 = fmaf(0.5f, th(2.5f * T2m2.x), 0.5f);
        float g01_1 = fmaf(0.5f, th(2.5f * T2m2.y), 0.5f);
        float g11_0 = fmaf(0.5f, th(2.5f * T3m2.x), 0.5f);
        float g11_1 = fmaf(0.5f, th(2.5f * T3m2.y), 0.5f);
        float gn11_0 = fmaf(0.5f, th(2.5f * T4m2.x), 0.5f);
        float gn11_1 = fmaf(0.5f, th(2.5f * T4m2.y), 0.5f);

        float s10_0 = fmaf(0.5f, th(d10[0]), 0.5f);
        float s10_1 = fmaf(0.5f, th(d10[1]), 0.5f);
        float s01_0 = fmaf(0.5f, th(d01[0]), 0.5f);
        float s01_1 = fmaf(0.5f, th(d01[1]), 0.5f);
        float s11_0 = fmaf(0.5f, th(d11[0]), 0.5f);
        float s11_1 = fmaf(0.5f, th(d11[1]), 0.5f);
        float sn11_0 = fmaf(0.5f, th(dn11[0]), 0.5f);
        float sn11_1 = fmaf(0.5f, th(dn11[1]), 0.5f);

        float a0 = g10_0 * s10_0,  a1 = g10_1 * s10_1;
        float b0 = g01_0 * s01_0,  b1 = g01_1 * s01_1;
        float e0 = g11_0 * s11_0,  e1 = g11_1 * s11_1;
        float f0 = gn11_0 * sn11_0, f1 = gn11_1 * sn11_1;

        *reinterpret_cast<float2*>(o + (0 << 18)) = make_float2(a0, a1);
        *reinterpret_cast<float2*>(o + (1 << 18)) = make_float2(g10_0 - a0, g10_1 - a1);
        *reinterpret_cast<float2*>(o + (2 << 18)) = make_float2(b0, b1);
        *reinterpret_cast<float2*>(o + (3 << 18)) = make_float2(b0, b1);   // e01n == e01
        *reinterpret_cast<float2*>(o + (4 << 18)) = make_float2(e0, e1);
        *reinterpret_cast<float2*>(o + (5 << 18)) = make_float2(g11_0 - e0, g11_1 - e1);
        *reinterpret_cast<float2*>(o + (6 << 18)) = make_float2(f0, f1);
        *reinterpret_cast<float2*>(o + (7 << 18)) = make_float2(gn11_0 - f0, gn11_1 - f1);
    }
}

extern "C" void kernel_launch(void* const* d_in, const int* in_sizes, int n_in,
                              void* d_out, int out_size) {
    const float* x = (const float*)d_in[0];
    float* out = (float*)d_out;
    int total_threads = 16 * 3 * HH * (WW / 2);
    edge_kernel<<<total_threads / 256, 256>>>(x, out);
}

// round 15
// speedup vs baseline: 1.7118x; 1.0752x over previous
#include <cuda_runtime.h>

// Edge_27547920236817: B=16, C=3, H=W=512 f32 in; out (B, C*8, H, W) f32.
// R14: back to the proven 1px/thread f32-tanh structure (occ ~88%), plus:
//  - copysign trick: s10/s11 reuse th(|d10|)/th(|d11|) from the ad-chain
//    (33 -> 31 MUFU tanh per pixel, -2 instr)
//  - 2D grid: blockIdx.y = b*3+c, no div/mod or plane decomposition in-thread.

#define HH 512
#define WW 512

__device__ __forceinline__ float th(float x) {
    float y;
    asm("tanh.approx.f32 %0, %1;" : "=f"(y) : "f"(x));
    return y;
}

__global__ void __launch_bounds__(256) edge_kernel(const float* __restrict__ in,
                                                   float* __restrict__ out) {
    int i  = blockIdx.x * blockDim.x + threadIdx.x;   // index within plane
    int x  = i & (WW - 1);
    int y  = i >> 9;
    int bc = blockIdx.y;          // b*3 + c
    int b  = bc / 3;
    int c  = bc - 3 * b;

    float* o = out + (((b * 24 + c * 8) << 18) + i);

    if (x < 2 || x >= WW - 2 || y < 2 || y >= HH - 2) {
        #pragma unroll
        for (int k = 0; k < 8; k++) o[k << 18] = 0.0f;
        return;
    }

    int cm = (c + 2) % 3;   // rl a=+1 -> channel (c-1)%3
    int cp = (c + 1) % 3;   // rl a=-1 -> channel (c+1)%3

    const float* p  = in + (bc << 18);
    const float* pa = in + ((b * 3 + cm) << 18);
    const float* pc = in + ((b * 3 + cp) << 18);

    int r   = i;
    int rm1 = r - WW, rp1 = r + WW, rm2 = r - 2 * WW;

    const float S = 5.0f;   // tanh-arg units: sigmoid(10t) = 0.5+0.5*tanh(5t)

    // own-channel neighborhood (scaled by 5)
    float v00   = S * __ldg(p + r);
    float vm1m1 = S * __ldg(p + rm1 - 1);
    float vm10  = S * __ldg(p + rm1);
    float vm1p1 = S * __ldg(p + rm1 + 1);
    float v0m1  = S * __ldg(p + r - 1);
    float v0p1  = S * __ldg(p + r + 1);
    float vp1m1 = S * __ldg(p + rp1 - 1);
    float vp10  = S * __ldg(p + rp1);
    float vp1p1 = S * __ldg(p + rp1 + 1);
    float vm20  = S * __ldg(p + rm2);

    // channel cm ( = (c-1) mod 3 )
    float a00   = S * __ldg(pa + r);
    float a0m1  = S * __ldg(pa + r - 1);
    float a0p1  = S * __ldg(pa + r + 1);
    float am10  = S * __ldg(pa + rm1);
    float am2p1 = S * __ldg(pa + rm2 + 1);
    float am2m1 = S * __ldg(pa + rm2 - 1);

    // channel cp ( = (c+1) mod 3 )
    float cm10  = S * __ldg(pc + rm1);
    float cm2m1 = S * __ldg(pc + rm2 - 1);
    float c0m1  = S * __ldg(pc + r - 1);

    // scaled diffs: diff_s = X(y-s0, x-s1) - X(y,x)
    float d10   = vm10  - v00;
    float dn10  = vp10  - v00;
    float d01   = v0m1  - v00;
    float dn01  = v0p1  - v00;
    float d11   = vm1m1 - v00;
    float dnn11 = vp1p1 - v00;
    float dn11  = vp1m1 - v00;
    float d1n1  = vm1p1 - v00;

    float rd01a  = a0m1 - a00;      // rl(.,(1,0))
    float rdn01a = a0p1 - a00;
    float rd10u  = vm20  - vm10;    // rl(.,(0,1))
    float rdn10u = v00   - vm10;
    float rd01u  = vm1m1 - vm10;
    float rdn11b = a0m1  - am10;    // rl(.,(1,1))
    float rd1n1b = am2p1 - am10;
    float rd11b  = am2m1 - am10;
    float rd11c  = cm2m1 - cm10;    // rl(.,(-1,1))
    float rdn11c = c0m1  - cm10;

    // ---- group 10 ----
    float ad10r = fabsf(d10);
    float t10a  = th(ad10r);                        // XU 1
    float ad10  = ad10r * fmaf(0.5f, t10a, 0.5f);
    float s10   = fmaf(0.5f, copysignf(t10a, d10), 0.5f);   // free sign sigmoid
    float T10 = th(ad10 - fabsf(d01)) + th(ad10 - fabsf(dn01)) + th(ad10 - fabsf(dn10))
              + 2.0f * th(ad10 - fabsf(rd01a)) + th(ad10 - fabsf(rdn01a));   // XU 5
    float g10 = fmaf(0.5f, th(fmaf(2.5f, T10, -5.0f)), 0.5f);               // XU 1
    float o0 = g10 * s10;
    float o1 = g10 - o0;

    // ---- group 01 (gated by MODIFIED ad10; e01n == e01 per reference) ----
    float ad01 = fabsf(d01) * fmaf(0.5f, th(ad10), 0.5f);                   // XU 1
    float T01 = th(ad01 - fabsf(d10)) + th(ad01 - fabsf(dn10)) + th(ad01 - fabsf(dn01))
              + th(ad01 - fabsf(rd10u)) + th(ad01 - fabsf(rdn10u)) + th(ad01 - fabsf(rd01u)); // XU 6
    float g01 = fmaf(0.5f, th(fmaf(2.5f, T01, -5.0f)), 0.5f);               // XU 1
    float s01 = fmaf(0.5f, th(d01), 0.5f);                                  // XU 1
    float o2 = g01 * s01;

    // ---- group 11 ----
    float ad11r = fabsf(d11);
    float t11a  = th(ad11r);                        // XU 1
    float ad11  = ad11r * fmaf(0.5f, t11a, 0.5f);
    float s11   = fmaf(0.5f, copysignf(t11a, d11), 0.5f);   // free sign sigmoid
    float T11 = th(ad11 - fabsf(dn11)) + th(ad11 - fabsf(d1n1)) + th(ad11 - fabsf(dnn11))
              + th(ad11 - fabsf(rdn11b)) + th(ad11 - fabsf(rd1n1b)) + th(ad11 - fabsf(rd11b)); // XU 6
    float g11 = fmaf(0.5f, th(fmaf(2.5f, T11, -5.0f)), 0.5f);               // XU 1
    float o4 = g11 * s11;
    float o5 = g11 - o4;

    // ---- group n11 (hard gate (ad>0) is identity on |.|) ----
    float adn11 = fabsf(dn11);
    float Tn11 = th(adn11 - fabsf(d11)) + th(adn11 - fabsf(d1n1)) + th(adn11 - fabsf(dnn11))
               + th(adn11 - fabsf(rd11c)) + 2.0f * th(adn11 - fabsf(rdn11c)); // XU 5
    float gn11 = fmaf(0.5f, th(fmaf(2.5f, Tn11, -5.0f)), 0.5f);             // XU 1
    float sn11 = fmaf(0.5f, th(dn11), 0.5f);                                // XU 1
    float o6 = gn11 * sn11;
    float o7 = gn11 - o6;

    o[0 << 18] = o0;
    o[1 << 18] = o1;
    o[2 << 18] = o2;
    o[3 << 18] = o2;     // reference quirk: e01n == e01
    o[4 << 18] = o4;
    o[5 << 18] = o5;
    o[6 << 18] = o6;
    o[7 << 18] = o7;
}

extern "C" void kernel_launch(void* const* d_in, const int* in_sizes, int n_in,
                              void* d_out, int out_size) {
    const float* x = (const float*)d_in[0];
    float* out = (float*)d_out;
    dim3 grid((HH * WW) / 256, 16 * 3);
    edge_kernel<<<grid, 256>>>(x, out);
}